// round 15
// baseline (speedup 1.0000x reference)
#include <cuda_runtime.h>
#include <cuda_fp16.h>
#include <stdint.h>

#define N_ 1024
#define S_ 8
#define I_ 128
#define F_ 1024
#define M_ 512

// fp16 scratch (converted once per launch)
__device__ __half g_xh[(size_t)N_ * S_ * I_];        // 1M  (x)
__device__ __half g_wgh[(size_t)3 * S_ * F_ * I_];   // 3M  (gate weights i,g,o)
__device__ __half g_wouth[(size_t)S_ * M_ * F_];     // 4M  (Wout)
__device__ __half g_h[(size_t)N_ * S_ * F_];         // 8M  (hidden)

// ---------------------------------------------------------------------------
// helpers
// ---------------------------------------------------------------------------
__device__ __forceinline__ uint32_t smem_u32(const void* p) {
    uint32_t a;
    asm("{ .reg .u64 t; cvta.to.shared.u64 t, %1; cvt.u32.u64 %0, t; }"
        : "=r"(a) : "l"(p));
    return a;
}
__device__ __forceinline__ void cp16(uint32_t dst, const void* src) {
    asm volatile("cp.async.cg.shared.global [%0], [%1], 16;" :: "r"(dst), "l"(src));
}
__device__ __forceinline__ void cp_commit() { asm volatile("cp.async.commit_group;"); }
template <int Nw> __device__ __forceinline__ void cp_wait() {
    asm volatile("cp.async.wait_group %0;" :: "n"(Nw));
}
__device__ __forceinline__ void ldsm4(uint32_t* r, uint32_t addr) {
    asm volatile("ldmatrix.sync.aligned.m8n8.x4.shared.b16 {%0,%1,%2,%3}, [%4];"
                 : "=r"(r[0]), "=r"(r[1]), "=r"(r[2]), "=r"(r[3]) : "r"(addr));
}
__device__ __forceinline__ void mma16816(float* c, const uint32_t* a, const uint32_t* b) {
    asm volatile(
        "mma.sync.aligned.m16n8k16.row.col.f32.f16.f16.f32 "
        "{%0,%1,%2,%3}, {%4,%5,%6,%7}, {%8,%9}, {%0,%1,%2,%3};"
        : "+f"(c[0]), "+f"(c[1]), "+f"(c[2]), "+f"(c[3])
        : "r"(a[0]), "r"(a[1]), "r"(a[2]), "r"(a[3]), "r"(b[0]), "r"(b[1]));
}
__device__ __forceinline__ float fexp(float x) {
    float y;
    asm("ex2.approx.f32 %0, %1;" : "=f"(y) : "f"(x * 1.4426950408889634f));
    return y;
}
__device__ __forceinline__ float frcp(float x) {
    float y;
    asm("rcp.approx.f32 %0, %1;" : "=f"(y) : "f"(x));
    return y;
}
__device__ __forceinline__ float sigmoid_f(float x) { return frcp(1.0f + fexp(-x)); }
__device__ __forceinline__ float tanh_f(float x)    { return 1.0f - 2.0f * frcp(1.0f + fexp(2.0f * x)); }

__device__ __forceinline__ uint32_t pack2h(__half a, __half b) {
    union { __half2 v; uint32_t u; } cv;
    cv.v = __halves2half2(a, b);
    return cv.u;
}
__device__ __forceinline__ uint4 cvt8h(const float* f) {
    uint4 H;
    uint32_t* Hp = (uint32_t*)&H;
#pragma unroll
    for (int j = 0; j < 4; ++j)
        Hp[j] = pack2h(__float2half_rn(f[j * 2]), __float2half_rn(f[j * 2 + 1]));
    return H;
}

// ---------------------------------------------------------------------------
// Kernel 0: convert everything to plain fp16. 2 items x 8 floats per thread,
// grid 2048 (halves launch overhead, doubles per-thread MLP).
// ---------------------------------------------------------------------------
__global__ __launch_bounds__(256) void convert_kernel(
    const float* __restrict__ x,
    const float* __restrict__ wi, const float* __restrict__ wg,
    const float* __restrict__ wo, const float* __restrict__ wout)
{
#pragma unroll
    for (int rep = 0; rep < 2; ++rep) {
        const int item = blockIdx.x * 256 + threadIdx.x + rep * 524288;  // 0..1048575
        const float* src;
        __half* dst;
        size_t off;
        if (item < 131072)      { src = x;    dst = g_xh;            off = (size_t)item * 8; }
        else if (item < 262144) { src = wi;   dst = g_wgh;           off = (size_t)(item - 131072) * 8; }
        else if (item < 393216) { src = wg;   dst = g_wgh + 1048576; off = (size_t)(item - 262144) * 8; }
        else if (item < 524288) { src = wo;   dst = g_wgh + 2097152; off = (size_t)(item - 393216) * 8; }
        else                    { src = wout; dst = g_wouth;         off = (size_t)(item - 524288) * 8; }
        float v[8];
        *(float4*)&v[0] = *(const float4*)&src[off + 0];
        *(float4*)&v[4] = *(const float4*)&src[off + 4];
        *(uint4*)&dst[off] = cvt8h(v);
    }
}

// ---------------------------------------------------------------------------
// Kernel A: gates (R6-exact). CTA = 128(n) x 64(f), 3 gates fused, single-pass
// fp16 mma. smem: A [128][136h], 3x B [64][136h]. 87040 B, occ 2.
// ---------------------------------------------------------------------------
#define GROWB 272
#define GSB   34816
#define GSBSZ 17408
#define GATES_SMEM 87040

__global__ __launch_bounds__(256, 2) void gates_mma(const float* __restrict__ bi,
                                                    const float* __restrict__ bg,
                                                    const float* __restrict__ bo)
{
    extern __shared__ char smem[];
    const uint32_t sb = smem_u32(smem);
    const int t = threadIdx.x;
    const int lane = t & 31, wid = t >> 5;
    const int wm = wid & 3;        // n group (4 x 32 rows)
    const int wn = wid >> 2;       // f group (2 x 32 cols)
    const int n0 = blockIdx.x * 128;
    const int f0 = blockIdx.y * 64;
    const int s  = blockIdx.z;

#pragma unroll
    for (int it = 0; it < 8; ++it) {
        int item = t + it * 256;               // 0..2047
        int row = item >> 4, seg = item & 15;
        cp16(sb + row * GROWB + seg * 16,
             g_xh + (size_t)(n0 + row) * (S_ * I_) + s * I_ + seg * 8);
    }
#pragma unroll
    for (int z = 0; z < 3; ++z) {
        const __half* wsrc = g_wgh + ((size_t)z * S_ + s) * F_ * I_;
#pragma unroll
        for (int it = 0; it < 4; ++it) {
            int item = t + it * 256;           // 0..1023: 64 rows x 16 segs
            int row = item >> 4, seg = item & 15;
            cp16(sb + GSB + z * GSBSZ + row * GROWB + seg * 16,
                 wsrc + (size_t)(f0 + row) * I_ + seg * 8);
        }
    }
    cp_commit();
    cp_wait<0>();
    __syncthreads();

    float C[3][8][4];
#pragma unroll
    for (int z = 0; z < 3; ++z)
#pragma unroll
        for (int i = 0; i < 8; ++i)
#pragma unroll
            for (int j = 0; j < 4; ++j) C[z][i][j] = 0.0f;

    const int a_row  = lane & 15;
    const int a_colb = (lane >> 4) * 16;
    const int b_row  = (lane & 7) + ((lane >> 4) & 1) * 8;
    const int b_colb = ((lane >> 3) & 1) * 16;

#pragma unroll
    for (int ks = 0; ks < 8; ++ks) {
        const int kb = ks * 32;
        uint32_t A[2][4];
#pragma unroll
        for (int mt = 0; mt < 2; ++mt)
            ldsm4(A[mt], sb + (wm * 32 + mt * 16 + a_row) * GROWB + a_colb + kb);
#pragma unroll
        for (int z = 0; z < 3; ++z) {
            uint32_t B[4][2];
#pragma unroll
            for (int p = 0; p < 2; ++p) {
                uint32_t r[4];
                ldsm4(r, sb + GSB + z * GSBSZ
                         + (wn * 32 + p * 16 + b_row) * GROWB + b_colb + kb);
                B[p * 2 + 0][0] = r[0]; B[p * 2 + 0][1] = r[1];
                B[p * 2 + 1][0] = r[2]; B[p * 2 + 1][1] = r[3];
            }
#pragma unroll
            for (int mt = 0; mt < 2; ++mt)
#pragma unroll
                for (int nt = 0; nt < 4; ++nt)
                    mma16816(C[z][mt * 4 + nt], A[mt], B[nt]);
        }
    }

#pragma unroll
    for (int mt = 0; mt < 2; ++mt) {
#pragma unroll
        for (int nt = 0; nt < 4; ++nt) {
            const int idx = mt * 4 + nt;
            const int r0 = n0 + wm * 32 + mt * 16 + (lane >> 2);
            const int f  = f0 + wn * 32 + nt * 8 + (lane & 3) * 2;
            float2 vbi = *(const float2*)&bi[s * F_ + f];
            float2 vbg = *(const float2*)&bg[s * F_ + f];
            float2 vbo = *(const float2*)&bo[s * F_ + f];
#pragma unroll
            for (int half = 0; half < 2; ++half) {
                const int r = r0 + half * 8;
                float pi0 = C[0][idx][half * 2 + 0] + vbi.x;
                float pi1 = C[0][idx][half * 2 + 1] + vbi.y;
                float pg0 = C[1][idx][half * 2 + 0] + vbg.x;
                float pg1 = C[1][idx][half * 2 + 1] + vbg.y;
                float po0 = C[2][idx][half * 2 + 0] + vbo.x;
                float po1 = C[2][idx][half * 2 + 1] + vbo.y;
                float h0 = sigmoid_f(po0) * tanh_f(sigmoid_f(pi0) * tanh_f(pg0));
                float h1 = sigmoid_f(po1) * tanh_f(sigmoid_f(pi1) * tanh_f(pg1));
                size_t ob = ((size_t)r * S_ + s) * F_ + f;
                *(uint32_t*)&g_h[ob] = pack2h(__float2half_rn(h0), __float2half_rn(h1));
            }
        }
    }
}

// ---------------------------------------------------------------------------
// Kernel B: out projection (R10-exact body + PDL preamble).
// CTA = 128(n) x 64(m): grid 512 = single balanced wave at occ 4.
// 8 warps: wm4 = wid>>1 (4 x 32 n-rows), wn2 = wid&1 (2 x 32 m-cols).
// K=1024 in 16 chunks of 64, 2-stage cp.async.
// smem/stage: A [128][72h] (18432) + B [64][72h] (9216) = 27648; x2 = 55296.
// ---------------------------------------------------------------------------
#define OROWB 144
#define OB_OFF 18432
#define OSTAGE 27648
#define OUT_SMEM 55296

__global__ __launch_bounds__(256, 4) void out_mma(const float* __restrict__ bout,
                                                  float* __restrict__ out)
{
    extern __shared__ char smem[];
    const uint32_t sb = smem_u32(smem);
    const int t = threadIdx.x;
    const int lane = t & 31, wid = t >> 5;
    const int wm4 = wid >> 1;      // n group (4 x 32 rows)
    const int wn2 = wid & 1;       // m group (2 x 32 cols)
    const int n0 = blockIdx.x * 128;
    const int m0 = blockIdx.y * 64;
    const int s  = blockIdx.z;

    // ---- PDL preamble: B chunk 0 (depends only on convert) ----
#pragma unroll
    for (int it = 0; it < 2; ++it) {
        int item = t + it * 256;               // 0..511: 64 rows x 8 segs
        int row = item >> 3, seg = item & 7;
        size_t bsrc = ((size_t)s * M_ + m0 + row) * F_ + seg * 8;
        cp16(sb + OB_OFF + row * OROWB + seg * 16, g_wouth + bsrc);
    }

    // ---- wait for gates grid (h visible after this) ----
    cudaGridDependencySynchronize();

    auto load_chunk = [&](int kc) {
        const uint32_t stg = sb + (kc & 1) * OSTAGE;
        const int k0 = kc * 64;
#pragma unroll
        for (int it = 0; it < 4; ++it) {
            int item = t + it * 256;           // 0..1023: 128 rows x 8 segs
            int row = item >> 3, seg = item & 7;
            size_t asrc = ((size_t)(n0 + row) * S_ + s) * F_ + k0 + seg * 8;
            cp16(stg + row * OROWB + seg * 16, g_h + asrc);
        }
#pragma unroll
        for (int it = 0; it < 2; ++it) {
            int item = t + it * 256;           // 0..511: 64 rows x 8 segs
            int row = item >> 3, seg = item & 7;
            size_t bsrc = ((size_t)s * M_ + m0 + row) * F_ + k0 + seg * 8;
            cp16(stg + OB_OFF + row * OROWB + seg * 16, g_wouth + bsrc);
        }
        cp_commit();
    };

    // A chunk 0 joins the pending preamble B0 in one commit group
    {
#pragma unroll
        for (int it = 0; it < 4; ++it) {
            int item = t + it * 256;
            int row = item >> 3, seg = item & 7;
            size_t asrc = ((size_t)(n0 + row) * S_ + s) * F_ + seg * 8;
            cp16(sb + row * OROWB + seg * 16, g_h + asrc);
        }
        cp_commit();                           // group0 = {B0, A0}
    }

    float C[8][4];
#pragma unroll
    for (int i = 0; i < 8; ++i)
#pragma unroll
        for (int j = 0; j < 4; ++j) C[i][j] = 0.0f;

    const int a_row  = lane & 15;
    const int a_colb = (lane >> 4) * 16;
    const int b_row  = (lane & 7) + ((lane >> 4) & 1) * 8;
    const int b_colb = ((lane >> 3) & 1) * 16;

    for (int kc = 0; kc < 16; ++kc) {
        if (kc < 15) { load_chunk(kc + 1); cp_wait<1>(); }
        else cp_wait<0>();
        __syncthreads();
        const uint32_t stg = sb + (kc & 1) * OSTAGE;
#pragma unroll
        for (int ks = 0; ks < 4; ++ks) {
            const int kb = ks * 32;
            uint32_t A[2][4];
#pragma unroll
            for (int mt = 0; mt < 2; ++mt)
                ldsm4(A[mt], stg + (wm4 * 32 + mt * 16 + a_row) * OROWB + a_colb + kb);
            uint32_t B[4][2];
#pragma unroll
            for (int p = 0; p < 2; ++p) {
                uint32_t rb = (wn2 * 32 + p * 16 + b_row) * OROWB + b_colb + kb;
                uint32_t r[4];
                ldsm4(r, stg + OB_OFF + rb);
                B[p * 2 + 0][0] = r[0]; B[p * 2 + 0][1] = r[1];
                B[p * 2 + 1][0] = r[2]; B[p * 2 + 1][1] = r[3];
            }
#pragma unroll
            for (int mt = 0; mt < 2; ++mt)
#pragma unroll
                for (int nt = 0; nt < 4; ++nt)
                    mma16816(C[mt * 4 + nt], A[mt], B[nt]);
        }
        __syncthreads();
    }

    // ---- epilogue: + bout, fp32 store ----
#pragma unroll
    for (int mt = 0; mt < 2; ++mt) {
#pragma unroll
        for (int nt = 0; nt < 4; ++nt) {
            const int idx = mt * 4 + nt;
            const int r0 = n0 + wm4 * 32 + mt * 16 + (lane >> 2);
            const int m  = m0 + wn2 * 32 + nt * 8 + (lane & 3) * 2;
            float2 vb = *(const float2*)&bout[s * M_ + m];
#pragma unroll
            for (int half = 0; half < 2; ++half) {
                const int r = r0 + half * 8;
                float2 ov;
                ov.x = C[idx][half * 2 + 0] + vb.x;
                ov.y = C[idx][half * 2 + 1] + vb.y;
                *(float2*)&out[(size_t)r * (S_ * M_) + s * M_ + m] = ov;
            }
        }
    }
}

// ---------------------------------------------------------------------------
// Launch. Inputs: modulation, Wxi, Whi, bi, Wxf, Whf, bf, Wxg, Whg, bg,
// Wxo, Who, bo, Wout, bout. Wh* unused (h0=0); Wxf/bf unused (c0=0).
// out_mma uses programmatic dependent launch on the gates->out edge.
// ---------------------------------------------------------------------------
extern "C" void kernel_launch(void* const* d_in, const int* in_sizes, int n_in,
                              void* d_out, int out_size)
{
    const float* mod  = (const float*)d_in[0];
    const float* Wxi  = (const float*)d_in[1];
    const float* bi   = (const float*)d_in[3];
    const float* Wxg  = (const float*)d_in[7];
    const float* bg   = (const float*)d_in[9];
    const float* Wxo  = (const float*)d_in[10];
    const float* bo   = (const float*)d_in[12];
    const float* Wout = (const float*)d_in[13];
    const float* bout = (const float*)d_in[14];
    float* out = (float*)d_out;

    cudaFuncSetAttribute(gates_mma, cudaFuncAttributeMaxDynamicSharedMemorySize, GATES_SMEM);
    cudaFuncSetAttribute(out_mma,   cudaFuncAttributeMaxDynamicSharedMemorySize, OUT_SMEM);

    convert_kernel<<<2048, 256>>>(mod, Wxi, Wxg, Wxo, Wout);
    gates_mma<<<dim3(8, 16, 8), 256, GATES_SMEM>>>(bi, bg, bo);

    // out_mma with programmatic stream serialization (PDL)
    cudaLaunchConfig_t cfg = {};
    cfg.gridDim = dim3(8, 8, 8);               // 512 CTAs = one balanced wave @ occ 4
    cfg.blockDim = dim3(256, 1, 1);
    cfg.dynamicSmemBytes = OUT_SMEM;
    cfg.stream = 0;
    cudaLaunchAttribute attrs[1];
    attrs[0].id = cudaLaunchAttributeProgrammaticStreamSerialization;
    attrs[0].val.programmaticStreamSerializationAllowed = 1;
    cfg.attrs = attrs;
    cfg.numAttrs = 1;
    cudaLaunchKernelEx(&cfg, out_mma, bout, out);
}

// round 16
// speedup vs baseline: 1.0253x; 1.0253x over previous
#include <cuda_runtime.h>
#include <cuda_fp16.h>
#include <stdint.h>

#define N_ 1024
#define S_ 8
#define I_ 128
#define F_ 1024
#define M_ 512

// fp16 scratch
__device__ __half g_xh[(size_t)N_ * S_ * I_];        // 1M  (x)
__device__ __half g_wgh[(size_t)3 * S_ * F_ * I_];   // 3M  (gate weights i,g,o)
__device__ __half g_wouth[(size_t)S_ * M_ * F_];     // 4M  (Wout; written by gates_mma)
__device__ __half g_h[(size_t)N_ * S_ * F_];         // 8M  (hidden)

// ---------------------------------------------------------------------------
// helpers
// ---------------------------------------------------------------------------
__device__ __forceinline__ uint32_t smem_u32(const void* p) {
    uint32_t a;
    asm("{ .reg .u64 t; cvta.to.shared.u64 t, %1; cvt.u32.u64 %0, t; }"
        : "=r"(a) : "l"(p));
    return a;
}
__device__ __forceinline__ void cp16(uint32_t dst, const void* src) {
    asm volatile("cp.async.cg.shared.global [%0], [%1], 16;" :: "r"(dst), "l"(src));
}
__device__ __forceinline__ void cp_commit() { asm volatile("cp.async.commit_group;"); }
template <int Nw> __device__ __forceinline__ void cp_wait() {
    asm volatile("cp.async.wait_group %0;" :: "n"(Nw));
}
__device__ __forceinline__ void ldsm4(uint32_t* r, uint32_t addr) {
    asm volatile("ldmatrix.sync.aligned.m8n8.x4.shared.b16 {%0,%1,%2,%3}, [%4];"
                 : "=r"(r[0]), "=r"(r[1]), "=r"(r[2]), "=r"(r[3]) : "r"(addr));
}
__device__ __forceinline__ void mma16816(float* c, const uint32_t* a, const uint32_t* b) {
    asm volatile(
        "mma.sync.aligned.m16n8k16.row.col.f32.f16.f16.f32 "
        "{%0,%1,%2,%3}, {%4,%5,%6,%7}, {%8,%9}, {%0,%1,%2,%3};"
        : "+f"(c[0]), "+f"(c[1]), "+f"(c[2]), "+f"(c[3])
        : "r"(a[0]), "r"(a[1]), "r"(a[2]), "r"(a[3]), "r"(b[0]), "r"(b[1]));
}
__device__ __forceinline__ float fexp(float x) {
    float y;
    asm("ex2.approx.f32 %0, %1;" : "=f"(y) : "f"(x * 1.4426950408889634f));
    return y;
}
__device__ __forceinline__ float frcp(float x) {
    float y;
    asm("rcp.approx.f32 %0, %1;" : "=f"(y) : "f"(x));
    return y;
}
__device__ __forceinline__ float sigmoid_f(float x) { return frcp(1.0f + fexp(-x)); }
__device__ __forceinline__ float tanh_f(float x)    { return 1.0f - 2.0f * frcp(1.0f + fexp(2.0f * x)); }

__device__ __forceinline__ uint32_t pack2h(__half a, __half b) {
    union { __half2 v; uint32_t u; } cv;
    cv.v = __halves2half2(a, b);
    return cv.u;
}
__device__ __forceinline__ uint4 cvt8h(const float* f) {
    uint4 H;
    uint32_t* Hp = (uint32_t*)&H;
#pragma unroll
    for (int j = 0; j < 4; ++j)
        Hp[j] = pack2h(__float2half_rn(f[j * 2]), __float2half_rn(f[j * 2 + 1]));
    return H;
}

// ---------------------------------------------------------------------------
// Kernel 0: mini-convert (x + gate weights only; R11-exact, measured 7.1us).
// ---------------------------------------------------------------------------
__global__ __launch_bounds__(256) void convert_kernel(
    const float* __restrict__ x,
    const float* __restrict__ wi, const float* __restrict__ wg,
    const float* __restrict__ wo)
{
    const int item = blockIdx.x * 256 + threadIdx.x;   // 0..524287
    const float* src;
    __half* dst;
    size_t off;
    if (item < 131072)      { src = x;  dst = g_xh;            off = (size_t)item * 8; }
    else if (item < 262144) { src = wi; dst = g_wgh;           off = (size_t)(item - 131072) * 8; }
    else if (item < 393216) { src = wg; dst = g_wgh + 1048576; off = (size_t)(item - 262144) * 8; }
    else                    { src = wo; dst = g_wgh + 2097152; off = (size_t)(item - 393216) * 8; }
    float v[8];
    *(float4*)&v[0] = *(const float4*)&src[off + 0];
    *(float4*)&v[4] = *(const float4*)&src[off + 4];
    *(uint4*)&dst[off] = cvt8h(v);
}

// ---------------------------------------------------------------------------
// Kernel A: gates (R6-exact) + hidden Wout side-conversion.
// Each of the 1024 CTAs converts a disjoint 4096-fp32 slice of Wout between
// its cp.async issue and cp_wait (latency hidden under the smem fill; DRAM
// bandwidth is idle in this HMMA-bound kernel).
// smem: A [128][136h], 3x B [64][136h]. 87040 B, occ 2.
// ---------------------------------------------------------------------------
#define GROWB 272
#define GSB   34816
#define GSBSZ 17408
#define GATES_SMEM 87040

__global__ __launch_bounds__(256, 2) void gates_mma(
    const float* __restrict__ Wout,
    const float* __restrict__ bi, const float* __restrict__ bg,
    const float* __restrict__ bo)
{
    extern __shared__ char smem[];
    const uint32_t sb = smem_u32(smem);
    const int t = threadIdx.x;
    const int lane = t & 31, wid = t >> 5;
    const int wm = wid & 3;        // n group (4 x 32 rows)
    const int wn = wid >> 2;       // f group (2 x 32 cols)
    const int n0 = blockIdx.x * 128;
    const int f0 = blockIdx.y * 64;
    const int s  = blockIdx.z;

    // ---- async smem fill (R6-exact) ----
#pragma unroll
    for (int it = 0; it < 8; ++it) {
        int item = t + it * 256;               // 0..2047
        int row = item >> 4, seg = item & 15;
        cp16(sb + row * GROWB + seg * 16,
             g_xh + (size_t)(n0 + row) * (S_ * I_) + s * I_ + seg * 8);
    }
#pragma unroll
    for (int z = 0; z < 3; ++z) {
        const __half* wsrc = g_wgh + ((size_t)z * S_ + s) * F_ * I_;
#pragma unroll
        for (int it = 0; it < 4; ++it) {
            int item = t + it * 256;           // 0..1023: 64 rows x 16 segs
            int row = item >> 4, seg = item & 15;
            cp16(sb + GSB + z * GSBSZ + row * GROWB + seg * 16,
                 wsrc + (size_t)(f0 + row) * I_ + seg * 8);
        }
    }
    cp_commit();

    // ---- Wout side-conversion slice (overlaps the cp.async fill) ----
    {
        const int cid = blockIdx.x + blockIdx.y * 8 + blockIdx.z * 128;  // 0..1023
        const size_t base = (size_t)cid * 4096 + t * 16;
        float v[16];
        *(float4*)&v[0]  = *(const float4*)&Wout[base + 0];
        *(float4*)&v[4]  = *(const float4*)&Wout[base + 4];
        *(float4*)&v[8]  = *(const float4*)&Wout[base + 8];
        *(float4*)&v[12] = *(const float4*)&Wout[base + 12];
        *(uint4*)&g_wouth[base + 0] = cvt8h(&v[0]);
        *(uint4*)&g_wouth[base + 8] = cvt8h(&v[8]);
    }

    cp_wait<0>();
    __syncthreads();

    // ---- compute (R6-exact) ----
    float C[3][8][4];
#pragma unroll
    for (int z = 0; z < 3; ++z)
#pragma unroll
        for (int i = 0; i < 8; ++i)
#pragma unroll
            for (int j = 0; j < 4; ++j) C[z][i][j] = 0.0f;

    const int a_row  = lane & 15;
    const int a_colb = (lane >> 4) * 16;
    const int b_row  = (lane & 7) + ((lane >> 4) & 1) * 8;
    const int b_colb = ((lane >> 3) & 1) * 16;

#pragma unroll
    for (int ks = 0; ks < 8; ++ks) {
        const int kb = ks * 32;
        uint32_t A[2][4];
#pragma unroll
        for (int mt = 0; mt < 2; ++mt)
            ldsm4(A[mt], sb + (wm * 32 + mt * 16 + a_row) * GROWB + a_colb + kb);
#pragma unroll
        for (int z = 0; z < 3; ++z) {
            uint32_t B[4][2];
#pragma unroll
            for (int p = 0; p < 2; ++p) {
                uint32_t r[4];
                ldsm4(r, sb + GSB + z * GSBSZ
                         + (wn * 32 + p * 16 + b_row) * GROWB + b_colb + kb);
                B[p * 2 + 0][0] = r[0]; B[p * 2 + 0][1] = r[1];
                B[p * 2 + 1][0] = r[2]; B[p * 2 + 1][1] = r[3];
            }
#pragma unroll
            for (int mt = 0; mt < 2; ++mt)
#pragma unroll
                for (int nt = 0; nt < 4; ++nt)
                    mma16816(C[z][mt * 4 + nt], A[mt], B[nt]);
        }
    }

    // ---- epilogue: bias + activations, h -> fp16 (R6-exact) ----
#pragma unroll
    for (int mt = 0; mt < 2; ++mt) {
#pragma unroll
        for (int nt = 0; nt < 4; ++nt) {
            const int idx = mt * 4 + nt;
            const int r0 = n0 + wm * 32 + mt * 16 + (lane >> 2);
            const int f  = f0 + wn * 32 + nt * 8 + (lane & 3) * 2;
            float2 vbi = *(const float2*)&bi[s * F_ + f];
            float2 vbg = *(const float2*)&bg[s * F_ + f];
            float2 vbo = *(const float2*)&bo[s * F_ + f];
#pragma unroll
            for (int half = 0; half < 2; ++half) {
                const int r = r0 + half * 8;
                float pi0 = C[0][idx][half * 2 + 0] + vbi.x;
                float pi1 = C[0][idx][half * 2 + 1] + vbi.y;
                float pg0 = C[1][idx][half * 2 + 0] + vbg.x;
                float pg1 = C[1][idx][half * 2 + 1] + vbg.y;
                float po0 = C[2][idx][half * 2 + 0] + vbo.x;
                float po1 = C[2][idx][half * 2 + 1] + vbo.y;
                float h0 = sigmoid_f(po0) * tanh_f(sigmoid_f(pi0) * tanh_f(pg0));
                float h1 = sigmoid_f(po1) * tanh_f(sigmoid_f(pi1) * tanh_f(pg1));
                size_t ob = ((size_t)r * S_ + s) * F_ + f;
                *(uint32_t*)&g_h[ob] = pack2h(__float2half_rn(h0), __float2half_rn(h1));
            }
        }
    }
}

// ---------------------------------------------------------------------------
// Kernel B: out projection (R6-exact body). PDL launch; ALL loads (incl. B
// from g_wouth, now produced by gates) happen after the grid sync.
// smem/stage: A [128][72h] + B [128][72h] = 36864; x2 = 73728; occ 2.
// ---------------------------------------------------------------------------
#define OROWB 144
#define OMATSZ 18432
#define OSTAGE 36864
#define OUT_SMEM 73728

__global__ __launch_bounds__(256, 2) void out_mma(const float* __restrict__ bout,
                                                  float* __restrict__ out)
{
    extern __shared__ char smem[];
    const uint32_t sb = smem_u32(smem);
    const int t = threadIdx.x;
    const int lane = t & 31, wid = t >> 5;
    const int wn4 = wid & 3;       // n group (4 x 32 rows)
    const int wm2 = wid >> 2;      // m group (2 x 64 cols)
    const int n0 = blockIdx.x * 128;
    const int m0 = blockIdx.y * 128;
    const int s  = blockIdx.z;

    // wait for gates (h AND g_wouth visible after this)
    cudaGridDependencySynchronize();

    auto load_chunk = [&](int kc) {
        const uint32_t stg = sb + (kc & 1) * OSTAGE;
        const int k0 = kc * 64;
#pragma unroll
        for (int it = 0; it < 4; ++it) {
            int item = t + it * 256;           // 0..1023: 128 rows x 8 segs
            int row = item >> 3, seg = item & 7;
            size_t asrc = ((size_t)(n0 + row) * S_ + s) * F_ + k0 + seg * 8;
            cp16(stg + 0 * OMATSZ + row * OROWB + seg * 16, g_h + asrc);
            size_t bsrc = ((size_t)s * M_ + m0 + row) * F_ + k0 + seg * 8;
            cp16(stg + 1 * OMATSZ + row * OROWB + seg * 16, g_wouth + bsrc);
        }
        cp_commit();
    };

    float C[16][4];
#pragma unroll
    for (int i = 0; i < 16; ++i)
#pragma unroll
        for (int j = 0; j < 4; ++j) C[i][j] = 0.0f;

    const int a_row  = lane & 15;
    const int a_colb = (lane >> 4) * 16;
    const int b_row  = (lane & 7) + ((lane >> 4) & 1) * 8;
    const int b_colb = ((lane >> 3) & 1) * 16;

    load_chunk(0);
    for (int kc = 0; kc < 16; ++kc) {
        if (kc < 15) { load_chunk(kc + 1); cp_wait<1>(); }
        else cp_wait<0>();
        __syncthreads();
        const uint32_t stg = sb + (kc & 1) * OSTAGE;
#pragma unroll
        for (int ks = 0; ks < 4; ++ks) {
            const int kb = ks * 32;
            uint32_t A[2][4];
#pragma unroll
            for (int mt = 0; mt < 2; ++mt)
                ldsm4(A[mt], stg + (wn4 * 32 + mt * 16 + a_row) * OROWB + a_colb + kb);
            uint32_t B[8][2];
#pragma unroll
            for (int p = 0; p < 4; ++p) {
                uint32_t rb = (wm2 * 64 + p * 16 + b_row) * OROWB + b_colb + kb;
                uint32_t r[4];
                ldsm4(r, stg + 1 * OMATSZ + rb);
                B[p * 2 + 0][0] = r[0]; B[p * 2 + 0][1] = r[1];
                B[p * 2 + 1][0] = r[2]; B[p * 2 + 1][1] = r[3];
            }
#pragma unroll
            for (int mt = 0; mt < 2; ++mt)
#pragma unroll
                for (int nt = 0; nt < 8; ++nt)
                    mma16816(C[mt * 8 + nt], A[mt], B[nt]);
        }
        __syncthreads();
    }

    // ---- epilogue: + bout, fp32 store ----
#pragma unroll
    for (int mt = 0; mt < 2; ++mt) {
#pragma unroll
        for (int nt = 0; nt < 8; ++nt) {
            const int idx = mt * 8 + nt;
            const int r0 = n0 + wn4 * 32 + mt * 16 + (lane >> 2);
            const int m  = m0 + wm2 * 64 + nt * 8 + (lane & 3) * 2;
            float2 vb = *(const float2*)&bout[s * M_ + m];
#pragma unroll
            for (int half = 0; half < 2; ++half) {
                const int r = r0 + half * 8;
                float2 ov;
                ov.x = C[idx][half * 2 + 0] + vb.x;
                ov.y = C[idx][half * 2 + 1] + vb.y;
                *(float2*)&out[(size_t)r * (S_ * M_) + s * M_ + m] = ov;
            }
        }
    }
}

// ---------------------------------------------------------------------------
// Launch. Inputs: modulation, Wxi, Whi, bi, Wxf, Whf, bf, Wxg, Whg, bg,
// Wxo, Who, bo, Wout, bout. Wh* unused (h0=0); Wxf/bf unused (c0=0).
// ---------------------------------------------------------------------------
extern "C" void kernel_launch(void* const* d_in, const int* in_sizes, int n_in,
                              void* d_out, int out_size)
{
    const float* mod  = (const float*)d_in[0];
    const float* Wxi  = (const float*)d_in[1];
    const float* bi   = (const float*)d_in[3];
    const float* Wxg  = (const float*)d_in[7];
    const float* bg   = (const float*)d_in[9];
    const float* Wxo  = (const float*)d_in[10];
    const float* bo   = (const float*)d_in[12];
    const float* Wout = (const float*)d_in[13];
    const float* bout = (const float*)d_in[14];
    float* out = (float*)d_out;

    cudaFuncSetAttribute(gates_mma, cudaFuncAttributeMaxDynamicSharedMemorySize, GATES_SMEM);
    cudaFuncSetAttribute(out_mma,   cudaFuncAttributeMaxDynamicSharedMemorySize, OUT_SMEM);

    convert_kernel<<<2048, 256>>>(mod, Wxi, Wxg, Wxo);
    gates_mma<<<dim3(8, 16, 8), 256, GATES_SMEM>>>(Wout, bi, bg, bo);

    // out_mma with programmatic stream serialization (PDL)
    cudaLaunchConfig_t cfg = {};
    cfg.gridDim = dim3(8, 4, 8);
    cfg.blockDim = dim3(256, 1, 1);
    cfg.dynamicSmemBytes = OUT_SMEM;
    cfg.stream = 0;
    cudaLaunchAttribute attrs[1];
    attrs[0].id = cudaLaunchAttributeProgrammaticStreamSerialization;
    attrs[0].val.programmaticStreamSerializationAllowed = 1;
    cfg.attrs = attrs;
    cfg.numAttrs = 1;
    cudaLaunchKernelEx(&cfg, out_mma, bout, out);
}

// round 17
// speedup vs baseline: 1.0317x; 1.0062x over previous
#include <cuda_runtime.h>
#include <cuda_fp16.h>
#include <stdint.h>

#define N_ 1024
#define S_ 8
#define I_ 128
#define F_ 1024
#define M_ 512

// fp16 scratch
__device__ __half g_xh[(size_t)N_ * S_ * I_];        // 1M  (x)
__device__ __half g_wgh[(size_t)3 * S_ * F_ * I_];   // 3M  (gate weights i,g,o)
__device__ __half g_wouth[(size_t)S_ * M_ * F_];     // 4M  (Wout; written by gates_mma)
__device__ __half g_h[(size_t)N_ * S_ * F_];         // 8M  (hidden)

// ---------------------------------------------------------------------------
// helpers
// ---------------------------------------------------------------------------
__device__ __forceinline__ uint32_t smem_u32(const void* p) {
    uint32_t a;
    asm("{ .reg .u64 t; cvta.to.shared.u64 t, %1; cvt.u32.u64 %0, t; }"
        : "=r"(a) : "l"(p));
    return a;
}
__device__ __forceinline__ void cp16(uint32_t dst, const void* src) {
    asm volatile("cp.async.cg.shared.global [%0], [%1], 16;" :: "r"(dst), "l"(src));
}
__device__ __forceinline__ void cp_commit() { asm volatile("cp.async.commit_group;"); }
template <int Nw> __device__ __forceinline__ void cp_wait() {
    asm volatile("cp.async.wait_group %0;" :: "n"(Nw));
}
__device__ __forceinline__ void ldsm4(uint32_t* r, uint32_t addr) {
    asm volatile("ldmatrix.sync.aligned.m8n8.x4.shared.b16 {%0,%1,%2,%3}, [%4];"
                 : "=r"(r[0]), "=r"(r[1]), "=r"(r[2]), "=r"(r[3]) : "r"(addr));
}
__device__ __forceinline__ void mma16816(float* c, const uint32_t* a, const uint32_t* b) {
    asm volatile(
        "mma.sync.aligned.m16n8k16.row.col.f32.f16.f16.f32 "
        "{%0,%1,%2,%3}, {%4,%5,%6,%7}, {%8,%9}, {%0,%1,%2,%3};"
        : "+f"(c[0]), "+f"(c[1]), "+f"(c[2]), "+f"(c[3])
        : "r"(a[0]), "r"(a[1]), "r"(a[2]), "r"(a[3]), "r"(b[0]), "r"(b[1]));
}
__device__ __forceinline__ float fexp(float x) {
    float y;
    asm("ex2.approx.f32 %0, %1;" : "=f"(y) : "f"(x * 1.4426950408889634f));
    return y;
}
__device__ __forceinline__ float frcp(float x) {
    float y;
    asm("rcp.approx.f32 %0, %1;" : "=f"(y) : "f"(x));
    return y;
}
__device__ __forceinline__ float sigmoid_f(float x) { return frcp(1.0f + fexp(-x)); }
__device__ __forceinline__ float tanh_f(float x)    { return 1.0f - 2.0f * frcp(1.0f + fexp(2.0f * x)); }

__device__ __forceinline__ uint32_t pack2h(__half a, __half b) {
    union { __half2 v; uint32_t u; } cv;
    cv.v = __halves2half2(a, b);
    return cv.u;
}
__device__ __forceinline__ uint4 cvt8h(const float* f) {
    uint4 H;
    uint32_t* Hp = (uint32_t*)&H;
#pragma unroll
    for (int j = 0; j < 4; ++j)
        Hp[j] = pack2h(__float2half_rn(f[j * 2]), __float2half_rn(f[j * 2 + 1]));
    return H;
}

// ---------------------------------------------------------------------------
// Kernel 0: mini-convert (x + gate weights only). R16-exact.
// ---------------------------------------------------------------------------
__global__ __launch_bounds__(256) void convert_kernel(
    const float* __restrict__ x,
    const float* __restrict__ wi, const float* __restrict__ wg,
    const float* __restrict__ wo)
{
    const int item = blockIdx.x * 256 + threadIdx.x;   // 0..524287
    const float* src;
    __half* dst;
    size_t off;
    if (item < 131072)      { src = x;  dst = g_xh;            off = (size_t)item * 8; }
    else if (item < 262144) { src = wi; dst = g_wgh;           off = (size_t)(item - 131072) * 8; }
    else if (item < 393216) { src = wg; dst = g_wgh + 1048576; off = (size_t)(item - 262144) * 8; }
    else                    { src = wo; dst = g_wgh + 2097152; off = (size_t)(item - 393216) * 8; }
    float v[8];
    *(float4*)&v[0] = *(const float4*)&src[off + 0];
    *(float4*)&v[4] = *(const float4*)&src[off + 4];
    *(uint4*)&dst[off] = cvt8h(v);
}

// ---------------------------------------------------------------------------
// Kernel A: gates (R16 body), PDL-launched. Order: Wout side-conversion slice
// (independent of convert — reads raw input Wout) BEFORE the grid sync, so it
// overlaps convert's drain and this grid's launch; then sync; then cp.async
// fill of x / gate-weight tiles (which DO depend on convert).
// smem: A [128][136h], 3x B [64][136h]. 87040 B, occ 2.
// ---------------------------------------------------------------------------
#define GROWB 272
#define GSB   34816
#define GSBSZ 17408
#define GATES_SMEM 87040

__global__ __launch_bounds__(256, 2) void gates_mma(
    const float* __restrict__ Wout,
    const float* __restrict__ bi, const float* __restrict__ bg,
    const float* __restrict__ bo)
{
    extern __shared__ char smem[];
    const uint32_t sb = smem_u32(smem);
    const int t = threadIdx.x;
    const int lane = t & 31, wid = t >> 5;
    const int wm = wid & 3;        // n group (4 x 32 rows)
    const int wn = wid >> 2;       // f group (2 x 32 cols)
    const int n0 = blockIdx.x * 128;
    const int f0 = blockIdx.y * 64;
    const int s  = blockIdx.z;

    // ---- PDL preamble: Wout side-conversion slice (no convert dependency) ----
    {
        const int cid = blockIdx.x + blockIdx.y * 8 + blockIdx.z * 128;  // 0..1023
        const size_t base = (size_t)cid * 4096 + t * 16;
        float v[16];
        *(float4*)&v[0]  = *(const float4*)&Wout[base + 0];
        *(float4*)&v[4]  = *(const float4*)&Wout[base + 4];
        *(float4*)&v[8]  = *(const float4*)&Wout[base + 8];
        *(float4*)&v[12] = *(const float4*)&Wout[base + 12];
        *(uint4*)&g_wouth[base + 0] = cvt8h(&v[0]);
        *(uint4*)&g_wouth[base + 8] = cvt8h(&v[8]);
    }

    // ---- wait for convert (g_xh / g_wgh visible after this) ----
    cudaGridDependencySynchronize();

    // ---- async smem fill (R6-exact) ----
#pragma unroll
    for (int it = 0; it < 8; ++it) {
        int item = t + it * 256;               // 0..2047
        int row = item >> 4, seg = item & 15;
        cp16(sb + row * GROWB + seg * 16,
             g_xh + (size_t)(n0 + row) * (S_ * I_) + s * I_ + seg * 8);
    }
#pragma unroll
    for (int z = 0; z < 3; ++z) {
        const __half* wsrc = g_wgh + ((size_t)z * S_ + s) * F_ * I_;
#pragma unroll
        for (int it = 0; it < 4; ++it) {
            int item = t + it * 256;           // 0..1023: 64 rows x 16 segs
            int row = item >> 4, seg = item & 15;
            cp16(sb + GSB + z * GSBSZ + row * GROWB + seg * 16,
                 wsrc + (size_t)(f0 + row) * I_ + seg * 8);
        }
    }
    cp_commit();
    cp_wait<0>();
    __syncthreads();

    // ---- compute (R6-exact) ----
    float C[3][8][4];
#pragma unroll
    for (int z = 0; z < 3; ++z)
#pragma unroll
        for (int i = 0; i < 8; ++i)
#pragma unroll
            for (int j = 0; j < 4; ++j) C[z][i][j] = 0.0f;

    const int a_row  = lane & 15;
    const int a_colb = (lane >> 4) * 16;
    const int b_row  = (lane & 7) + ((lane >> 4) & 1) * 8;
    const int b_colb = ((lane >> 3) & 1) * 16;

#pragma unroll
    for (int ks = 0; ks < 8; ++ks) {
        const int kb = ks * 32;
        uint32_t A[2][4];
#pragma unroll
        for (int mt = 0; mt < 2; ++mt)
            ldsm4(A[mt], sb + (wm * 32 + mt * 16 + a_row) * GROWB + a_colb + kb);
#pragma unroll
        for (int z = 0; z < 3; ++z) {
            uint32_t B[4][2];
#pragma unroll
            for (int p = 0; p < 2; ++p) {
                uint32_t r[4];
                ldsm4(r, sb + GSB + z * GSBSZ
                         + (wn * 32 + p * 16 + b_row) * GROWB + b_colb + kb);
                B[p * 2 + 0][0] = r[0]; B[p * 2 + 0][1] = r[1];
                B[p * 2 + 1][0] = r[2]; B[p * 2 + 1][1] = r[3];
            }
#pragma unroll
            for (int mt = 0; mt < 2; ++mt)
#pragma unroll
                for (int nt = 0; nt < 4; ++nt)
                    mma16816(C[z][mt * 4 + nt], A[mt], B[nt]);
        }
    }

    // ---- epilogue: bias + activations, h -> fp16 (R6-exact) ----
#pragma unroll
    for (int mt = 0; mt < 2; ++mt) {
#pragma unroll
        for (int nt = 0; nt < 4; ++nt) {
            const int idx = mt * 4 + nt;
            const int r0 = n0 + wm * 32 + mt * 16 + (lane >> 2);
            const int f  = f0 + wn * 32 + nt * 8 + (lane & 3) * 2;
            float2 vbi = *(const float2*)&bi[s * F_ + f];
            float2 vbg = *(const float2*)&bg[s * F_ + f];
            float2 vbo = *(const float2*)&bo[s * F_ + f];
#pragma unroll
            for (int half = 0; half < 2; ++half) {
                const int r = r0 + half * 8;
                float pi0 = C[0][idx][half * 2 + 0] + vbi.x;
                float pi1 = C[0][idx][half * 2 + 1] + vbi.y;
                float pg0 = C[1][idx][half * 2 + 0] + vbg.x;
                float pg1 = C[1][idx][half * 2 + 1] + vbg.y;
                float po0 = C[2][idx][half * 2 + 0] + vbo.x;
                float po1 = C[2][idx][half * 2 + 1] + vbo.y;
                float h0 = sigmoid_f(po0) * tanh_f(sigmoid_f(pi0) * tanh_f(pg0));
                float h1 = sigmoid_f(po1) * tanh_f(sigmoid_f(pi1) * tanh_f(pg1));
                size_t ob = ((size_t)r * S_ + s) * F_ + f;
                *(uint32_t*)&g_h[ob] = pack2h(__float2half_rn(h0), __float2half_rn(h1));
            }
        }
    }
}

// ---------------------------------------------------------------------------
// Kernel B: out projection (R16-exact). PDL launch; all loads after grid sync
// (g_h and g_wouth are both produced by gates).
// smem/stage: A [128][72h] + B [128][72h] = 36864; x2 = 73728; occ 2.
// ---------------------------------------------------------------------------
#define OROWB 144
#define OMATSZ 18432
#define OSTAGE 36864
#define OUT_SMEM 73728

__global__ __launch_bounds__(256, 2) void out_mma(const float* __restrict__ bout,
                                                  float* __restrict__ out)
{
    extern __shared__ char smem[];
    const uint32_t sb = smem_u32(smem);
    const int t = threadIdx.x;
    const int lane = t & 31, wid = t >> 5;
    const int wn4 = wid & 3;       // n group (4 x 32 rows)
    const int wm2 = wid >> 2;      // m group (2 x 64 cols)
    const int n0 = blockIdx.x * 128;
    const int m0 = blockIdx.y * 128;
    const int s  = blockIdx.z;

    cudaGridDependencySynchronize();

    auto load_chunk = [&](int kc) {
        const uint32_t stg = sb + (kc & 1) * OSTAGE;
        const int k0 = kc * 64;
#pragma unroll
        for (int it = 0; it < 4; ++it) {
            int item = t + it * 256;           // 0..1023: 128 rows x 8 segs
            int row = item >> 3, seg = item & 7;
            size_t asrc = ((size_t)(n0 + row) * S_ + s) * F_ + k0 + seg * 8;
            cp16(stg + 0 * OMATSZ + row * OROWB + seg * 16, g_h + asrc);
            size_t bsrc = ((size_t)s * M_ + m0 + row) * F_ + k0 + seg * 8;
            cp16(stg + 1 * OMATSZ + row * OROWB + seg * 16, g_wouth + bsrc);
        }
        cp_commit();
    };

    float C[16][4];
#pragma unroll
    for (int i = 0; i < 16; ++i)
#pragma unroll
        for (int j = 0; j < 4; ++j) C[i][j] = 0.0f;

    const int a_row  = lane & 15;
    const int a_colb = (lane >> 4) * 16;
    const int b_row  = (lane & 7) + ((lane >> 4) & 1) * 8;
    const int b_colb = ((lane >> 3) & 1) * 16;

    load_chunk(0);
    for (int kc = 0; kc < 16; ++kc) {
        if (kc < 15) { load_chunk(kc + 1); cp_wait<1>(); }
        else cp_wait<0>();
        __syncthreads();
        const uint32_t stg = sb + (kc & 1) * OSTAGE;
#pragma unroll
        for (int ks = 0; ks < 4; ++ks) {
            const int kb = ks * 32;
            uint32_t A[2][4];
#pragma unroll
            for (int mt = 0; mt < 2; ++mt)
                ldsm4(A[mt], stg + (wn4 * 32 + mt * 16 + a_row) * OROWB + a_colb + kb);
            uint32_t B[8][2];
#pragma unroll
            for (int p = 0; p < 4; ++p) {
                uint32_t rb = (wm2 * 64 + p * 16 + b_row) * OROWB + b_colb + kb;
                uint32_t r[4];
                ldsm4(r, stg + 1 * OMATSZ + rb);
                B[p * 2 + 0][0] = r[0]; B[p * 2 + 0][1] = r[1];
                B[p * 2 + 1][0] = r[2]; B[p * 2 + 1][1] = r[3];
            }
#pragma unroll
            for (int mt = 0; mt < 2; ++mt)
#pragma unroll
                for (int nt = 0; nt < 8; ++nt)
                    mma16816(C[mt * 8 + nt], A[mt], B[nt]);
        }
        __syncthreads();
    }

    // ---- epilogue: + bout, fp32 store ----
#pragma unroll
    for (int mt = 0; mt < 2; ++mt) {
#pragma unroll
        for (int nt = 0; nt < 8; ++nt) {
            const int idx = mt * 8 + nt;
            const int r0 = n0 + wn4 * 32 + mt * 16 + (lane >> 2);
            const int m  = m0 + wm2 * 64 + nt * 8 + (lane & 3) * 2;
            float2 vb = *(const float2*)&bout[s * M_ + m];
#pragma unroll
            for (int half = 0; half < 2; ++half) {
                const int r = r0 + half * 8;
                float2 ov;
                ov.x = C[idx][half * 2 + 0] + vb.x;
                ov.y = C[idx][half * 2 + 1] + vb.y;
                *(float2*)&out[(size_t)r * (S_ * M_) + s * M_ + m] = ov;
            }
        }
    }
}

// ---------------------------------------------------------------------------
// Launch. Inputs: modulation, Wxi, Whi, bi, Wxf, Whf, bf, Wxg, Whg, bg,
// Wxo, Who, bo, Wout, bout. Wh* unused (h0=0); Wxf/bf unused (c0=0).
// PDL chain: convert -> gates -> out (programmatic stream serialization).
// ---------------------------------------------------------------------------
extern "C" void kernel_launch(void* const* d_in, const int* in_sizes, int n_in,
                              void* d_out, int out_size)
{
    const float* mod  = (const float*)d_in[0];
    const float* Wxi  = (const float*)d_in[1];
    const float* bi   = (const float*)d_in[3];
    const float* Wxg  = (const float*)d_in[7];
    const float* bg   = (const float*)d_in[9];
    const float* Wxo  = (const float*)d_in[10];
    const float* bo   = (const float*)d_in[12];
    const float* Wout = (const float*)d_in[13];
    const float* bout = (const float*)d_in[14];
    float* out = (float*)d_out;

    cudaFuncSetAttribute(gates_mma, cudaFuncAttributeMaxDynamicSharedMemorySize, GATES_SMEM);
    cudaFuncSetAttribute(out_mma,   cudaFuncAttributeMaxDynamicSharedMemorySize, OUT_SMEM);

    convert_kernel<<<2048, 256>>>(mod, Wxi, Wxg, Wxo);

    cudaLaunchAttribute attrs[1];
    attrs[0].id = cudaLaunchAttributeProgrammaticStreamSerialization;
    attrs[0].val.programmaticStreamSerializationAllowed = 1;

    // gates_mma with PDL (preamble = Wout side-conversion)
    {
        cudaLaunchConfig_t cfg = {};
        cfg.gridDim = dim3(8, 16, 8);
        cfg.blockDim = dim3(256, 1, 1);
        cfg.dynamicSmemBytes = GATES_SMEM;
        cfg.stream = 0;
        cfg.attrs = attrs;
        cfg.numAttrs = 1;
        cudaLaunchKernelEx(&cfg, gates_mma, Wout, bi, bg, bo);
    }

    // out_mma with PDL
    {
        cudaLaunchConfig_t cfg = {};
        cfg.gridDim = dim3(8, 4, 8);
        cfg.blockDim = dim3(256, 1, 1);
        cfg.dynamicSmemBytes = OUT_SMEM;
        cfg.stream = 0;
        cfg.attrs = attrs;
        cfg.numAttrs = 1;
        cudaLaunchKernelEx(&cfg, out_mma, bout, out);
    }
}